// round 15
// baseline (speedup 1.0000x reference)
#include <cuda_runtime.h>
#include <cuda_fp16.h>
#include <cstdint>
#include <math.h>

#define Bn 8
#define Cn 128
#define Hn 64
#define Wn 64
#define On 128
#define K2 9
#define HW 4096
#define CK 1152
#define NCH 18

// ---------------- scratch ----------------
__device__ __half g_xt[Bn * HW * Cn];                  // NHWC fp16, channel-permuted per 64-block
// main A frags fp16 (hi only): [it18][mw4][kt4][mt2][lane32][16B] = 16KB/it
__device__ __align__(16) unsigned char g_Amain[NCH * 16384];
// off A frags (hi only): [it18][mt2][kt4][lane32][16B] = 4KB/it
__device__ __align__(16) unsigned char g_Aoff[NCH * 4096];

// k_main smem (bytes): B bufs 2 x (64 pos x 160B) = 20480; taps 2 x 2048; om_s 27*64*4
#define BPITCH 160
#define SMB(s)    ((s) * 10240)
#define SM_TAPS(tb) (20480 + (tb) * 2048)
#define OM_S      24576
#define SM_TOTAL  31488

// ---------------- helpers ----------------
__device__ __forceinline__ uint32_t pack2h(float v0, float v1) {
    __half2 H = __floats2half2_rn(v0, v1);
    return *(uint32_t*)&H;
}
__device__ __forceinline__ void mma_f16(float* d, const uint32_t* a, uint32_t b0, uint32_t b1) {
    asm volatile(
        "mma.sync.aligned.m16n8k16.row.col.f32.f16.f16.f32 "
        "{%0,%1,%2,%3},{%4,%5,%6,%7},{%8,%9},{%0,%1,%2,%3};"
        : "+f"(d[0]), "+f"(d[1]), "+f"(d[2]), "+f"(d[3])
        : "r"(a[0]), "r"(a[1]), "r"(a[2]), "r"(a[3]), "r"(b0), "r"(b1));
}
__device__ __forceinline__ void acc8(float* r, uint4 q, float wt) {
    const __half2* hh = (const __half2*)&q;
#pragma unroll
    for (int e = 0; e < 4; e++) {
        float2 f = __half22float2(hh[e]);
        r[e * 2]     = fmaf(wt, f.x, r[e * 2]);
        r[e * 2 + 1] = fmaf(wt, f.y, r[e * 2 + 1]);
    }
}
// channel permutation within each 64-block (lc even)
__device__ __forceinline__ int permq(int lc) {
    int kt = lc >> 4, k = lc & 15;
    if (k < 8) return (kt * 4 + (k >> 1)) * 4;
    return (kt * 4 + ((k - 8) >> 1)) * 4 + 2;
}

// ---------------- fused kernel: x transpose + weight prep ----------------
__global__ __launch_bounds__(256) void k_xt_prep(const float* __restrict__ x,
                                                 const float* __restrict__ wmain,
                                                 const float* __restrict__ woff,
                                                 const float* __restrict__ wmsk) {
    if (blockIdx.x < 4096) {
        __shared__ float sm[32][33];
        const int t = threadIdx.x;
        const int blk_id = blockIdx.x;
        const int hwb = blk_id & 127, cb4 = (blk_id >> 7) & 3, b = blk_id >> 9;
        const int hw0 = hwb * 32, c0 = cb4 * 32;
        const float* xb = x + (size_t)b * Cn * HW;
        __half* xtb = g_xt + (size_t)b * HW * Cn;
        {
            const int cr = t >> 3, f4 = t & 7;
            float4 v = *(const float4*)(xb + (size_t)(c0 + cr) * HW + hw0 + f4 * 4);
            sm[cr][f4 * 4 + 0] = v.x;
            sm[cr][f4 * 4 + 1] = v.y;
            sm[cr][f4 * 4 + 2] = v.z;
            sm[cr][f4 * 4 + 3] = v.w;
        }
        __syncthreads();
        // vectorized store: each 32-channel block maps to a contiguous 64B region
        if (t < 128) {
            const int hwl = t >> 2, grp = t & 3;
            uint32_t p[4];
#pragma unroll
            for (int gi = 0; gi < 2; gi++) {
                int qi = grp * 2 + gi;
                int kt = qi >> 2, g = qi & 3;
                float v0 = sm[kt * 16 + g * 2 + 0][hwl];
                float v1 = sm[kt * 16 + g * 2 + 1][hwl];
                float v2 = sm[kt * 16 + 8 + g * 2 + 0][hwl];
                float v3 = sm[kt * 16 + 8 + g * 2 + 1][hwl];
                p[gi * 2 + 0] = pack2h(v0, v1);
                p[gi * 2 + 1] = pack2h(v2, v3);
            }
            int blk = c0 >> 6, base = (cb4 & 1) * 32;
            *(uint4*)(xtb + (size_t)(hw0 + hwl) * Cn + blk * 64 + base + grp * 8) =
                make_uint4(p[0], p[1], p[2], p[3]);
        }
        return;
    }
    int i = (blockIdx.x - 4096) * 256 + threadIdx.x;
    if (i < 18432) {
        int lane = i & 31, mt = (i >> 5) & 1, kt = (i >> 6) & 3, mw = (i >> 8) & 3, it = i >> 10;
        int gid = lane >> 2, tig = lane & 3;
        int j = it >> 1, ch = it & 1;
        int r0 = mw * 32 + mt * 16 + gid;
        int cb = ch * 64 + kt * 16 + tig * 2;
        float wv[2][4];
#pragma unroll
        for (int rr = 0; rr < 2; rr++) {
            int r = r0 + rr * 8;
#pragma unroll
            for (int cc = 0; cc < 4; cc++) {
                int c = cb + (cc >> 1) * 8 + (cc & 1);
                wv[rr][cc] = wmain[(size_t)r * CK + c * K2 + j];
            }
        }
        uint4 hi;
        hi.x = pack2h(wv[0][0], wv[0][1]);
        hi.y = pack2h(wv[1][0], wv[1][1]);
        hi.z = pack2h(wv[0][2], wv[0][3]);
        hi.w = pack2h(wv[1][2], wv[1][3]);
        size_t base = (size_t)it * 16384 + (size_t)((mw * 4 + kt) * 2 + mt) * 512 + lane * 16;
        *(uint4*)(g_Amain + base) = hi;
    } else if (i < 18432 + 4608) {
        int q = i - 18432;
        int lane = q & 31, kt = (q >> 5) & 3, mt = (q >> 7) & 1, it = q >> 8;
        int gid = lane >> 2, tig = lane & 3;
        int j = it >> 1, ch = it & 1;
        int r0 = mt * 16 + gid;
        int cb = ch * 64 + kt * 16 + tig * 2;
        float wv[2][4];
#pragma unroll
        for (int rr = 0; rr < 2; rr++) {
            int r = r0 + rr * 8;
#pragma unroll
            for (int cc = 0; cc < 4; cc++) {
                int c = cb + (cc >> 1) * 8 + (cc & 1);
                float v = 0.f;
                if (r < 18)      v = woff[(size_t)r * CK + c * K2 + j];
                else if (r < 27) v = wmsk[(size_t)(r - 18) * CK + c * K2 + j];
                wv[rr][cc] = v;
            }
        }
        uint4 hi;
        hi.x = pack2h(wv[0][0], wv[0][1]);
        hi.y = pack2h(wv[1][0], wv[1][1]);
        hi.z = pack2h(wv[0][2], wv[0][3]);
        hi.w = pack2h(wv[1][2], wv[1][3]);
        size_t base = (size_t)it * 4096 + (size_t)(mt * 4 + kt) * 512 + lane * 16;
        *(uint4*)(g_Aoff + base) = hi;
    }
}

// ---------------- k_main: tap compute (64 pos, one row) — reads om from SMEM ----------------
__device__ __forceinline__ void tap_compute(const float* om_s, float* tb,
                                            int t, int ho, int j) {
    if (t >= 64) return;
    int col = t;
    int jy = j / 3, jx = j - jy * 3;
    float dy = om_s[(2 * j) * 64 + col];
    float dx = om_s[(2 * j + 1) * 64 + col];
    float m  = om_s[(18 + j) * 64 + col];
    float py = dy + (float)(jy + ho - 1);
    float px = dx + (float)(jx + col - 1);
    float y0f = floorf(py), x0f = floorf(px);
    float ly = py - y0f, lx = px - x0f;
    int y0 = (int)y0f, x0 = (int)x0f;
    int4 ti; float4 tw;
    {
        int yy = y0, xx = x0;
        bool v = (yy >= 0) && (yy < Hn) && (xx >= 0) && (xx < Wn);
        ti.x = min(max(yy, 0), Hn - 1) * Wn + min(max(xx, 0), Wn - 1);
        tw.x = v ? (1.f - ly) * (1.f - lx) * m : 0.f;
    }
    {
        int yy = y0, xx = x0 + 1;
        bool v = (yy >= 0) && (yy < Hn) && (xx >= 0) && (xx < Wn);
        ti.y = min(max(yy, 0), Hn - 1) * Wn + min(max(xx, 0), Wn - 1);
        tw.y = v ? (1.f - ly) * lx * m : 0.f;
    }
    {
        int yy = y0 + 1, xx = x0;
        bool v = (yy >= 0) && (yy < Hn) && (xx >= 0) && (xx < Wn);
        ti.z = min(max(yy, 0), Hn - 1) * Wn + min(max(xx, 0), Wn - 1);
        tw.z = v ? ly * (1.f - lx) * m : 0.f;
    }
    {
        int yy = y0 + 1, xx = x0 + 1;
        bool v = (yy >= 0) && (yy < Hn) && (xx >= 0) && (xx < Wn);
        ti.w = min(max(yy, 0), Hn - 1) * Wn + min(max(xx, 0), Wn - 1);
        tw.w = v ? ly * lx * m : 0.f;
    }
    *(int4*)(tb + col * 8) = ti;
    *(float4*)(tb + col * 8 + 4) = tw;
}

// ---------------- kernel: fused offmask prologue + deformable gather + HMMA ----------------
// 256 threads = 8 warps (mw 0..3 x nw 0..1). Warp tile M=32 x N=32. 3 CTAs/SM.
__global__ __launch_bounds__(256, 3) void k_main_mma(
    const float* __restrict__ b_off, const float* __restrict__ b_msk,
    float* __restrict__ out)
{
    extern __shared__ __align__(16) char smem[];
    const int t = threadIdx.x, w = t >> 5, lane = t & 31;
    const int gid = lane >> 2, tig = lane & 3;
    const int mw = w & 3, nw = w >> 2;
    const int gpos8 = t >> 3, gu8 = t & 7;
    const int b = blockIdx.x >> 6, ho = blockIdx.x & 63;
    const __half* xtb = g_xt + (size_t)b * HW * Cn;
    float* om_s = (float*)(smem + OM_S);

    // ---- offmask prologue: each warp computes 27 ch x 8 positions ----
    {
        float oacc[2][4];
#pragma unroll
        for (int mt = 0; mt < 2; mt++)
#pragma unroll
            for (int r = 0; r < 4; r++) oacc[mt][r] = 0.f;
        const int pos = w * 8 + gid;
        for (int it = 0; it < NCH; it++) {
            const int j = it >> 1, ch = it & 1;
            const int jy = j / 3, jx = j - jy * 3;
            const unsigned char* gb = g_Aoff + (size_t)it * 4096 + lane * 16;
            const int sy = ho + jy - 1, sx = pos + jx - 1;
            const bool valid = ((unsigned)sy < Hn) && ((unsigned)sx < Wn);
            const char* src = (const char*)(xtb + (size_t)(valid ? sy * Wn + sx : 0) * Cn + ch * 64);
#pragma unroll
            for (int kt = 0; kt < 4; kt++) {
                uint4 a0 = __ldg((const uint4*)(gb + (size_t)(0 * 4 + kt) * 512));
                uint4 a1 = __ldg((const uint4*)(gb + (size_t)(1 * 4 + kt) * 512));
                uint2 bv = make_uint2(0u, 0u);
                if (valid) bv = *(const uint2*)(src + (kt * 4 + tig) * 8);
                mma_f16(oacc[0], (const uint32_t*)&a0, bv.x, bv.y);
                mma_f16(oacc[1], (const uint32_t*)&a1, bv.x, bv.y);
            }
        }
#pragma unroll
        for (int mt = 0; mt < 2; mt++)
#pragma unroll
            for (int rr = 0; rr < 2; rr++) {
                int o = mt * 16 + gid + rr * 8;
                if (o >= 27) continue;
                float bias = (o < 18) ? __ldg(b_off + o) : __ldg(b_msk + o - 18);
                float v0 = oacc[mt][rr * 2 + 0] + bias;
                float v1 = oacc[mt][rr * 2 + 1] + bias;
                if (o >= 18) {
                    v0 = 1.f / (1.f + __expf(-v0));
                    v1 = 1.f / (1.f + __expf(-v1));
                }
                *(float2*)(om_s + o * 64 + w * 8 + 2 * tig) = make_float2(v0, v1);
            }
    }
    __syncthreads();

    float acc[2][4][4];
#pragma unroll
    for (int mt = 0; mt < 2; mt++)
#pragma unroll
        for (int nt = 0; nt < 4; nt++)
#pragma unroll
            for (int r = 0; r < 4; r++) acc[mt][nt][r] = 0.f;

    tap_compute(om_s, (float*)(smem + SM_TAPS(0)), t, ho, 0);
    __syncthreads();

    for (int it = 0; it < NCH; it++) {
        const int s = it & 1;
        const int j = it >> 1, ch = it & 1;
        // fill B[s]: gather (8 lanes/position) + combine + STS
        {
            const float* tpb = (const float*)(smem + SM_TAPS(j & 1));
            const __half* xg = xtb + ch * 64 + gu8 * 8;
            int4 ti0 = *(const int4*)(tpb + gpos8 * 8);
            float4 tw0 = *(const float4*)(tpb + gpos8 * 8 + 4);
            int4 ti1 = *(const int4*)(tpb + (gpos8 + 32) * 8);
            float4 tw1 = *(const float4*)(tpb + (gpos8 + 32) * 8 + 4);
            uint4 u[8];
            u[0] = __ldg((const uint4*)(xg + (size_t)ti0.x * Cn));
            u[1] = __ldg((const uint4*)(xg + (size_t)ti0.y * Cn));
            u[2] = __ldg((const uint4*)(xg + (size_t)ti0.z * Cn));
            u[3] = __ldg((const uint4*)(xg + (size_t)ti0.w * Cn));
            u[4] = __ldg((const uint4*)(xg + (size_t)ti1.x * Cn));
            u[5] = __ldg((const uint4*)(xg + (size_t)ti1.y * Cn));
            u[6] = __ldg((const uint4*)(xg + (size_t)ti1.z * Cn));
            u[7] = __ldg((const uint4*)(xg + (size_t)ti1.w * Cn));
            char* bd = smem + SMB(s);
            {
                float r[8] = {0, 0, 0, 0, 0, 0, 0, 0};
                acc8(r, u[0], tw0.x); acc8(r, u[1], tw0.y);
                acc8(r, u[2], tw0.z); acc8(r, u[3], tw0.w);
                __half2 o0 = __floats2half2_rn(r[0], r[1]), o1 = __floats2half2_rn(r[2], r[3]);
                __half2 o2 = __floats2half2_rn(r[4], r[5]), o3 = __floats2half2_rn(r[6], r[7]);
                *(uint4*)(bd + gpos8 * BPITCH + gu8 * 16) =
                    make_uint4(*(uint32_t*)&o0, *(uint32_t*)&o1, *(uint32_t*)&o2, *(uint32_t*)&o3);
            }
            {
                float r[8] = {0, 0, 0, 0, 0, 0, 0, 0};
                acc8(r, u[4], tw1.x); acc8(r, u[5], tw1.y);
                acc8(r, u[6], tw1.z); acc8(r, u[7], tw1.w);
                __half2 o0 = __floats2half2_rn(r[0], r[1]), o1 = __floats2half2_rn(r[2], r[3]);
                __half2 o2 = __floats2half2_rn(r[4], r[5]), o3 = __floats2half2_rn(r[6], r[7]);
                *(uint4*)(bd + (gpos8 + 32) * BPITCH + gu8 * 16) =
                    make_uint4(*(uint32_t*)&o0, *(uint32_t*)&o1, *(uint32_t*)&o2, *(uint32_t*)&o3);
            }
            if (ch == 1 && j < 8)
                tap_compute(om_s, (float*)(smem + SM_TAPS((j + 1) & 1)), t, ho, j + 1);
        }
        __syncthreads();
        // mma on B[s]; fill(it+1) targets B[s^1], so no trailing sync needed
        const char* bs = smem + SMB(s);
        const unsigned char* gA = g_Amain + (size_t)it * 16384 + (size_t)mw * 4096 + lane * 16;
#pragma unroll
        for (int kt = 0; kt < 4; kt++) {
            uint4 aH0 = __ldg((const uint4*)(gA + kt * 1024));
            uint4 aH1 = __ldg((const uint4*)(gA + kt * 1024 + 512));
#pragma unroll
            for (int nt = 0; nt < 4; nt++) {
                uint2 bv = *(const uint2*)(bs + (nw * 32 + nt * 8 + gid) * BPITCH + (kt * 4 + tig) * 8);
                mma_f16(acc[0][nt], (const uint32_t*)&aH0, bv.x, bv.y);
                mma_f16(acc[1][nt], (const uint32_t*)&aH1, bv.x, bv.y);
            }
        }
    }
    __syncthreads();

    // epilogue: two halves of 64 output channels, staged via smem (pitch 68 floats, 16B-aligned)
    float* ob = out + (size_t)b * On * HW + (size_t)ho * Wn;
    float* stage = (float*)smem;
#pragma unroll
    for (int half = 0; half < 2; half++) {
        if ((mw >> 1) == half) {
            int rbase = (mw & 1) * 32 + gid;
#pragma unroll
            for (int mt = 0; mt < 2; mt++)
#pragma unroll
                for (int nt = 0; nt < 4; nt++) {
                    int p0 = nw * 32 + nt * 8 + 2 * tig;
                    *(float2*)(stage + (rbase + mt * 16) * 68 + p0) =
                        make_float2(acc[mt][nt][0], acc[mt][nt][1]);
                    *(float2*)(stage + (rbase + mt * 16 + 8) * 68 + p0) =
                        make_float2(acc[mt][nt][2], acc[mt][nt][3]);
                }
        }
        __syncthreads();
#pragma unroll
        for (int e = t; e < 1024; e += 256) {
            int o = e >> 4, q = e & 15;
            float4 v = *(float4*)(stage + o * 68 + q * 4);
            *(float4*)(ob + (size_t)(half * 64 + o) * HW + q * 4) = v;
        }
        __syncthreads();
    }
}

// ---------------- launch ----------------
extern "C" void kernel_launch(void* const* d_in, const int* in_sizes, int n_in,
                              void* d_out, int out_size) {
    const float* x      = (const float*)d_in[0];
    const float* w_off  = (const float*)d_in[1];
    const float* b_off  = (const float*)d_in[2];
    const float* w_msk  = (const float*)d_in[3];
    const float* b_msk  = (const float*)d_in[4];
    const float* weight = (const float*)d_in[5];
    float* out = (float*)d_out;

    k_xt_prep<<<4096 + 90, 256>>>(x, weight, w_off, w_msk);
    k_main_mma<<<Bn * 64, 256, SM_TOTAL>>>(b_off, b_msk, out);
}

// round 16
// speedup vs baseline: 1.0062x; 1.0062x over previous
#include <cuda_runtime.h>
#include <cuda_fp16.h>
#include <cstdint>
#include <math.h>

#define Bn 8
#define Cn 128
#define Hn 64
#define Wn 64
#define On 128
#define K2 9
#define HW 4096
#define CK 1152
#define NCH 18

// ---------------- scratch ----------------
__device__ float g_offmask[Bn * 27 * HW];
__device__ __half g_xt[Bn * HW * Cn];                  // NHWC fp16, channel-permuted per 64-block
// main A frags fp16 (hi only): [it18][mw4][kt4][mt2][lane32][16B] = 16KB/it
__device__ __align__(16) unsigned char g_Amain[NCH * 16384];
// off A frags (hi only): [it18][mt2][kt4][lane32][16B] = 4KB/it
__device__ __align__(16) unsigned char g_Aoff[NCH * 4096];

// k_main smem (bytes): B bufs 2 x (64 pos x 160B) = 20480; taps 2 x 2048
#define BPITCH 160
#define SMB(s)    ((s) * 10240)
#define SM_TAPS(tb) (20480 + (tb) * 2048)
#define SM_TOTAL 24576

// ---------------- helpers ----------------
__device__ __forceinline__ uint32_t pack2h(float v0, float v1) {
    __half2 H = __floats2half2_rn(v0, v1);
    return *(uint32_t*)&H;
}
__device__ __forceinline__ void mma_f16(float* d, const uint32_t* a, uint32_t b0, uint32_t b1) {
    asm volatile(
        "mma.sync.aligned.m16n8k16.row.col.f32.f16.f16.f32 "
        "{%0,%1,%2,%3},{%4,%5,%6,%7},{%8,%9},{%0,%1,%2,%3};"
        : "+f"(d[0]), "+f"(d[1]), "+f"(d[2]), "+f"(d[3])
        : "r"(a[0]), "r"(a[1]), "r"(a[2]), "r"(a[3]), "r"(b0), "r"(b1));
}
__device__ __forceinline__ void acc8(float* r, uint4 q, float wt) {
    const __half2* hh = (const __half2*)&q;
#pragma unroll
    for (int e = 0; e < 4; e++) {
        float2 f = __half22float2(hh[e]);
        r[e * 2]     = fmaf(wt, f.x, r[e * 2]);
        r[e * 2 + 1] = fmaf(wt, f.y, r[e * 2 + 1]);
    }
}
// channel permutation within each 64-block (lc even)
__device__ __forceinline__ int permq(int lc) {
    int kt = lc >> 4, k = lc & 15;
    if (k < 8) return (kt * 4 + (k >> 1)) * 4;
    return (kt * 4 + ((k - 8) >> 1)) * 4 + 2;
}

// ---------------- fused kernel: x transpose + weight prep ----------------
__global__ __launch_bounds__(256) void k_xt_prep(const float* __restrict__ x,
                                                 const float* __restrict__ wmain,
                                                 const float* __restrict__ woff,
                                                 const float* __restrict__ wmsk) {
    if (blockIdx.x < 4096) {
        __shared__ float sm[32][33];
        const int t = threadIdx.x;
        const int blk_id = blockIdx.x;
        const int hwb = blk_id & 127, cb4 = (blk_id >> 7) & 3, b = blk_id >> 9;
        const int hw0 = hwb * 32, c0 = cb4 * 32;
        const float* xb = x + (size_t)b * Cn * HW;
        __half* xtb = g_xt + (size_t)b * HW * Cn;
        {
            const int cr = t >> 3, f4 = t & 7;
            float4 v = *(const float4*)(xb + (size_t)(c0 + cr) * HW + hw0 + f4 * 4);
            sm[cr][f4 * 4 + 0] = v.x;
            sm[cr][f4 * 4 + 1] = v.y;
            sm[cr][f4 * 4 + 2] = v.z;
            sm[cr][f4 * 4 + 3] = v.w;
        }
        __syncthreads();
        // vectorized store: each 32-channel block maps to a contiguous 64B region
        if (t < 128) {
            const int hwl = t >> 2, grp = t & 3;
            uint32_t p[4];
#pragma unroll
            for (int gi = 0; gi < 2; gi++) {
                int qi = grp * 2 + gi;
                int kt = qi >> 2, g = qi & 3;
                float v0 = sm[kt * 16 + g * 2 + 0][hwl];
                float v1 = sm[kt * 16 + g * 2 + 1][hwl];
                float v2 = sm[kt * 16 + 8 + g * 2 + 0][hwl];
                float v3 = sm[kt * 16 + 8 + g * 2 + 1][hwl];
                p[gi * 2 + 0] = pack2h(v0, v1);
                p[gi * 2 + 1] = pack2h(v2, v3);
            }
            int blk = c0 >> 6, base = (cb4 & 1) * 32;
            *(uint4*)(xtb + (size_t)(hw0 + hwl) * Cn + blk * 64 + base + grp * 8) =
                make_uint4(p[0], p[1], p[2], p[3]);
        }
        return;
    }
    int i = (blockIdx.x - 4096) * 256 + threadIdx.x;
    if (i < 18432) {
        int lane = i & 31, mt = (i >> 5) & 1, kt = (i >> 6) & 3, mw = (i >> 8) & 3, it = i >> 10;
        int gid = lane >> 2, tig = lane & 3;
        int j = it >> 1, ch = it & 1;
        int r0 = mw * 32 + mt * 16 + gid;
        int cb = ch * 64 + kt * 16 + tig * 2;
        float wv[2][4];
#pragma unroll
        for (int rr = 0; rr < 2; rr++) {
            int r = r0 + rr * 8;
#pragma unroll
            for (int cc = 0; cc < 4; cc++) {
                int c = cb + (cc >> 1) * 8 + (cc & 1);
                wv[rr][cc] = wmain[(size_t)r * CK + c * K2 + j];
            }
        }
        uint4 hi;
        hi.x = pack2h(wv[0][0], wv[0][1]);
        hi.y = pack2h(wv[1][0], wv[1][1]);
        hi.z = pack2h(wv[0][2], wv[0][3]);
        hi.w = pack2h(wv[1][2], wv[1][3]);
        size_t base = (size_t)it * 16384 + (size_t)((mw * 4 + kt) * 2 + mt) * 512 + lane * 16;
        *(uint4*)(g_Amain + base) = hi;
    } else if (i < 18432 + 4608) {
        int q = i - 18432;
        int lane = q & 31, kt = (q >> 5) & 3, mt = (q >> 7) & 1, it = q >> 8;
        int gid = lane >> 2, tig = lane & 3;
        int j = it >> 1, ch = it & 1;
        int r0 = mt * 16 + gid;
        int cb = ch * 64 + kt * 16 + tig * 2;
        float wv[2][4];
#pragma unroll
        for (int rr = 0; rr < 2; rr++) {
            int r = r0 + rr * 8;
#pragma unroll
            for (int cc = 0; cc < 4; cc++) {
                int c = cb + (cc >> 1) * 8 + (cc & 1);
                float v = 0.f;
                if (r < 18)      v = woff[(size_t)r * CK + c * K2 + j];
                else if (r < 27) v = wmsk[(size_t)(r - 18) * CK + c * K2 + j];
                wv[rr][cc] = v;
            }
        }
        uint4 hi;
        hi.x = pack2h(wv[0][0], wv[0][1]);
        hi.y = pack2h(wv[1][0], wv[1][1]);
        hi.z = pack2h(wv[0][2], wv[0][3]);
        hi.w = pack2h(wv[1][2], wv[1][3]);
        size_t base = (size_t)it * 4096 + (size_t)(mt * 4 + kt) * 512 + lane * 16;
        *(uint4*)(g_Aoff + base) = hi;
    }
}

// ---------------- kernel: offset+mask conv (fp16 1-term HMMA) ----------------
// 128 threads = 4 warps, warp tile M=32 x N=32; CTA covers 2 rows (128 pos). 256 CTAs.
__global__ __launch_bounds__(128) void k_offmask_mma(
    const float* __restrict__ b_off, const float* __restrict__ b_msk)
{
    const int t = threadIdx.x, w = t >> 5, lane = t & 31;
    const int gid = lane >> 2, tig = lane & 3;
    const int b = blockIdx.x >> 5, rp = blockIdx.x & 31, ho0 = rp * 2;
    const __half* xtb = g_xt + (size_t)b * HW * Cn;

    float acc[2][4][4];
#pragma unroll
    for (int mt = 0; mt < 2; mt++)
#pragma unroll
        for (int nt = 0; nt < 4; nt++)
#pragma unroll
            for (int r = 0; r < 4; r++) acc[mt][nt][r] = 0.f;

    for (int it = 0; it < NCH; it++) {
        const int j = it >> 1, ch = it & 1;
        const int jy = j / 3, jx = j - jy * 3;
        uint4 aH[2][4];
        {
            const unsigned char* gb = g_Aoff + (size_t)it * 4096 + lane * 16;
#pragma unroll
            for (int mt = 0; mt < 2; mt++)
#pragma unroll
                for (int kt = 0; kt < 4; kt++)
                    aH[mt][kt] = __ldg((const uint4*)(gb + (size_t)(mt * 4 + kt) * 512));
        }
#pragma unroll
        for (int nt = 0; nt < 4; nt++) {
            int pos = w * 32 + nt * 8 + gid;
            int row = ho0 + (pos >> 6), col = pos & 63;
            int sy = row + jy - 1, sx = col + jx - 1;
            bool valid = ((unsigned)sy < Hn) && ((unsigned)sx < Wn);
            const char* src = (const char*)(xtb + (size_t)(valid ? sy * Wn + sx : 0) * Cn + ch * 64);
#pragma unroll
            for (int kt = 0; kt < 4; kt++) {
                uint2 bv = make_uint2(0u, 0u);
                if (valid) bv = *(const uint2*)(src + (kt * 4 + tig) * 8);
#pragma unroll
                for (int mt = 0; mt < 2; mt++)
                    mma_f16(acc[mt][nt], (const uint32_t*)&aH[mt][kt], bv.x, bv.y);
            }
        }
    }
    float* om = g_offmask + (size_t)b * 27 * HW;
#pragma unroll
    for (int mt = 0; mt < 2; mt++)
#pragma unroll
        for (int rr = 0; rr < 2; rr++) {
            int o = mt * 16 + gid + rr * 8;
            if (o >= 27) continue;
            float bias = (o < 18) ? __ldg(b_off + o) : __ldg(b_msk + o - 18);
#pragma unroll
            for (int nt = 0; nt < 4; nt++) {
                int pos = w * 32 + nt * 8 + 2 * tig;
                int gp = (ho0 + (pos >> 6)) * Wn + (pos & 63);
                float v0 = acc[mt][nt][rr * 2 + 0] + bias;
                float v1 = acc[mt][nt][rr * 2 + 1] + bias;
                if (o >= 18) {
                    v0 = 1.f / (1.f + __expf(-v0));
                    v1 = 1.f / (1.f + __expf(-v1));
                }
                *(float2*)(om + (size_t)o * HW + gp) = make_float2(v0, v1);
            }
        }
}

// ---------------- k_main: tap compute (64 pos, one row) ----------------
__device__ __forceinline__ void tap_compute(const float* __restrict__ om, float* tb,
                                            int t, int ho, int j) {
    if (t >= 64) return;
    int col = t;
    int gp = ho * Wn + col;
    int jy = j / 3, jx = j - jy * 3;
    float dy = __ldg(om + (size_t)(2 * j) * HW + gp);
    float dx = __ldg(om + (size_t)(2 * j + 1) * HW + gp);
    float m  = __ldg(om + (size_t)(18 + j) * HW + gp);
    float py = dy + (float)(jy + ho - 1);
    float px = dx + (float)(jx + col - 1);
    float y0f = floorf(py), x0f = floorf(px);
    float ly = py - y0f, lx = px - x0f;
    int y0 = (int)y0f, x0 = (int)x0f;
    int4 ti; float4 tw;
    {
        int yy = y0, xx = x0;
        bool v = (yy >= 0) && (yy < Hn) && (xx >= 0) && (xx < Wn);
        ti.x = min(max(yy, 0), Hn - 1) * Wn + min(max(xx, 0), Wn - 1);
        tw.x = v ? (1.f - ly) * (1.f - lx) * m : 0.f;
    }
    {
        int yy = y0, xx = x0 + 1;
        bool v = (yy >= 0) && (yy < Hn) && (xx >= 0) && (xx < Wn);
        ti.y = min(max(yy, 0), Hn - 1) * Wn + min(max(xx, 0), Wn - 1);
        tw.y = v ? (1.f - ly) * lx * m : 0.f;
    }
    {
        int yy = y0 + 1, xx = x0;
        bool v = (yy >= 0) && (yy < Hn) && (xx >= 0) && (xx < Wn);
        ti.z = min(max(yy, 0), Hn - 1) * Wn + min(max(xx, 0), Wn - 1);
        tw.z = v ? ly * (1.f - lx) * m : 0.f;
    }
    {
        int yy = y0 + 1, xx = x0 + 1;
        bool v = (yy >= 0) && (yy < Hn) && (xx >= 0) && (xx < Wn);
        ti.w = min(max(yy, 0), Hn - 1) * Wn + min(max(xx, 0), Wn - 1);
        tw.w = v ? ly * lx * m : 0.f;
    }
    *(int4*)(tb + col * 8) = ti;
    *(float4*)(tb + col * 8 + 4) = tw;
}

// ---------------- kernel: deformable gather + fp16 1-term HMMA ----------------
// 256 threads = 8 warps (mw 0..3 x nw 0..1). Warp tile M=32 x N=32. 3 CTAs/SM.
// Gather: 8 lanes per position (one full 128B line per tap per instruction).
__global__ __launch_bounds__(256, 3) void k_main_mma(float* __restrict__ out)
{
    extern __shared__ __align__(16) char smem[];
    const int t = threadIdx.x, w = t >> 5, lane = t & 31;
    const int gid = lane >> 2, tig = lane & 3;
    const int mw = w & 3, nw = w >> 2;
    const int gpos8 = t >> 3, gu8 = t & 7;
    const int b = blockIdx.x >> 6, ho = blockIdx.x & 63;
    const __half* xtb = g_xt + (size_t)b * HW * Cn;
    const float* om = g_offmask + (size_t)b * 27 * HW;

    float acc[2][4][4];
#pragma unroll
    for (int mt = 0; mt < 2; mt++)
#pragma unroll
        for (int nt = 0; nt < 4; nt++)
#pragma unroll
            for (int r = 0; r < 4; r++) acc[mt][nt][r] = 0.f;

    tap_compute(om, (float*)(smem + SM_TAPS(0)), t, ho, 0);
    __syncthreads();

    for (int it = 0; it < NCH; it++) {
        const int s = it & 1;
        const int j = it >> 1, ch = it & 1;
        // fill B[s]: gather (8 lanes/position) + combine + STS
        {
            const float* tpb = (const float*)(smem + SM_TAPS(j & 1));
            const __half* xg = xtb + ch * 64 + gu8 * 8;
            int4 ti0 = *(const int4*)(tpb + gpos8 * 8);
            float4 tw0 = *(const float4*)(tpb + gpos8 * 8 + 4);
            int4 ti1 = *(const int4*)(tpb + (gpos8 + 32) * 8);
            float4 tw1 = *(const float4*)(tpb + (gpos8 + 32) * 8 + 4);
            uint4 u[8];
            u[0] = __ldg((const uint4*)(xg + (size_t)ti0.x * Cn));
            u[1] = __ldg((const uint4*)(xg + (size_t)ti0.y * Cn));
            u[2] = __ldg((const uint4*)(xg + (size_t)ti0.z * Cn));
            u[3] = __ldg((const uint4*)(xg + (size_t)ti0.w * Cn));
            u[4] = __ldg((const uint4*)(xg + (size_t)ti1.x * Cn));
            u[5] = __ldg((const uint4*)(xg + (size_t)ti1.y * Cn));
            u[6] = __ldg((const uint4*)(xg + (size_t)ti1.z * Cn));
            u[7] = __ldg((const uint4*)(xg + (size_t)ti1.w * Cn));
            char* bd = smem + SMB(s);
            {
                float r[8] = {0, 0, 0, 0, 0, 0, 0, 0};
                acc8(r, u[0], tw0.x); acc8(r, u[1], tw0.y);
                acc8(r, u[2], tw0.z); acc8(r, u[3], tw0.w);
                __half2 o0 = __floats2half2_rn(r[0], r[1]), o1 = __floats2half2_rn(r[2], r[3]);
                __half2 o2 = __floats2half2_rn(r[4], r[5]), o3 = __floats2half2_rn(r[6], r[7]);
                *(uint4*)(bd + gpos8 * BPITCH + gu8 * 16) =
                    make_uint4(*(uint32_t*)&o0, *(uint32_t*)&o1, *(uint32_t*)&o2, *(uint32_t*)&o3);
            }
            {
                float r[8] = {0, 0, 0, 0, 0, 0, 0, 0};
                acc8(r, u[4], tw1.x); acc8(r, u[5], tw1.y);
                acc8(r, u[6], tw1.z); acc8(r, u[7], tw1.w);
                __half2 o0 = __floats2half2_rn(r[0], r[1]), o1 = __floats2half2_rn(r[2], r[3]);
                __half2 o2 = __floats2half2_rn(r[4], r[5]), o3 = __floats2half2_rn(r[6], r[7]);
                *(uint4*)(bd + (gpos8 + 32) * BPITCH + gu8 * 16) =
                    make_uint4(*(uint32_t*)&o0, *(uint32_t*)&o1, *(uint32_t*)&o2, *(uint32_t*)&o3);
            }
            // compute next j's taps during odd-it fill (double-buffered, 2 syncs from readers)
            if (ch == 1 && j < 8)
                tap_compute(om, (float*)(smem + SM_TAPS((j + 1) & 1)), t, ho, j + 1);
        }
        __syncthreads();
        // mma on B[s]; fill(it+1) targets B[s^1], so no trailing sync needed
        const char* bs = smem + SMB(s);
        const unsigned char* gA = g_Amain + (size_t)it * 16384 + (size_t)mw * 4096 + lane * 16;
#pragma unroll
        for (int kt = 0; kt < 4; kt++) {
            uint4 aH0 = __ldg((const uint4*)(gA + kt * 1024));
            uint4 aH1 = __ldg((const uint4*)(gA + kt * 1024 + 512));
#pragma unroll
            for (int nt = 0; nt < 4; nt++) {
                uint2 bv = *(const uint2*)(bs + (nw * 32 + nt * 8 + gid) * BPITCH + (kt * 4 + tig) * 8);
                mma_f16(acc[0][nt], (const uint32_t*)&aH0, bv.x, bv.y);
                mma_f16(acc[1][nt], (const uint32_t*)&aH1, bv.x, bv.y);
            }
        }
    }
    __syncthreads();

    // epilogue: two halves of 64 output channels, staged via smem (pitch 68 floats, 16B-aligned)
    float* ob = out + (size_t)b * On * HW + (size_t)ho * Wn;
    float* stage = (float*)smem;
#pragma unroll
    for (int half = 0; half < 2; half++) {
        if ((mw >> 1) == half) {
            int rbase = (mw & 1) * 32 + gid;
#pragma unroll
            for (int mt = 0; mt < 2; mt++)
#pragma unroll
                for (int nt = 0; nt < 4; nt++) {
                    int p0 = nw * 32 + nt * 8 + 2 * tig;
                    *(float2*)(stage + (rbase + mt * 16) * 68 + p0) =
                        make_float2(acc[mt][nt][0], acc[mt][nt][1]);
                    *(float2*)(stage + (rbase + mt * 16 + 8) * 68 + p0) =
                        make_float2(acc[mt][nt][2], acc[mt][nt][3]);
                }
        }
        __syncthreads();
#pragma unroll
        for (int e = t; e < 1024; e += 256) {
            int o = e >> 4, q = e & 15;
            float4 v = *(float4*)(stage + o * 68 + q * 4);
            *(float4*)(ob + (size_t)(half * 64 + o) * HW + q * 4) = v;
        }
        __syncthreads();
    }
}

// ---------------- launch ----------------
extern "C" void kernel_launch(void* const* d_in, const int* in_sizes, int n_in,
                              void* d_out, int out_size) {
    const float* x      = (const float*)d_in[0];
    const float* w_off  = (const float*)d_in[1];
    const float* b_off  = (const float*)d_in[2];
    const float* w_msk  = (const float*)d_in[3];
    const float* b_msk  = (const float*)d_in[4];
    const float* weight = (const float*)d_in[5];
    float* out = (float*)d_out;

    k_xt_prep<<<4096 + 90, 256>>>(x, weight, w_off, w_msk);
    k_offmask_mma<<<Bn * 32, 128>>>(b_off, b_msk);
    k_main_mma<<<Bn * 64, 256, SM_TOTAL>>>(out);
}